// round 3
// baseline (speedup 1.0000x reference)
#include <cuda_runtime.h>

// Problem constants (fixed by the reference)
#define BGRAPH   512
#define MNODE    200
#define EPG      6400          // edges per graph (E/B)
#define DIMIN    128
#define KTOP     30
#define NTHREADS 256
#define NWARP    (NTHREADS/32)
#define S3       33            // padded stride for h1..h3 (bank-conflict-free gathers)

// SMEM layout (bytes):
//   h1,h2,h3 : 3 * 200*33 floats = 79200 B
//   yb       : 200*32 floats    = 25600 B   (also conv scratch after layer 4)
//   dinv,h4,y4: 600 floats      =  2400 B
//   start[201], cnt[200] ints   =  1604 B   (cnt reused as pos, then as ordx)
//   srt u8[6400]                =  6400 B
#define SM_FLOATS (3*MNODE*S3 + MNODE*32 + 3*MNODE)
#define SM_BYTES  (SM_FLOATS*4 + (201+200)*4 + EPG)

__global__ __launch_bounds__(NTHREADS)
void dgcnn_fused_kernel(const float* __restrict__ x,
                        const int*   __restrict__ esrc,
                        const int*   __restrict__ edst,
                        const float* __restrict__ W1, const float* __restrict__ b1,
                        const float* __restrict__ W2, const float* __restrict__ b2,
                        const float* __restrict__ W3, const float* __restrict__ b3,
                        const float* __restrict__ W4, const float* __restrict__ b4,
                        const float* __restrict__ cW1, const float* __restrict__ cb1,
                        const float* __restrict__ cW2, const float* __restrict__ cb2,
                        const float* __restrict__ lW1, const float* __restrict__ lb1,
                        const float* __restrict__ lW2, const float* __restrict__ lb2,
                        float* __restrict__ out)
{
    extern __shared__ char smem[];
    float* h1   = (float*)smem;             // [200][33]
    float* h2   = h1 + MNODE*S3;
    float* h3   = h2 + MNODE*S3;
    float* yb   = h3 + MNODE*S3;            // [200][32] scratch / y buffer
    float* dinv = yb + MNODE*32;            // [200]
    float* h4   = dinv + MNODE;             // [200]
    float* y4   = h4 + MNODE;               // [200]
    int*   start = (int*)(y4 + MNODE);      // [201]
    int*   cnt   = start + 201;             // [200] (pos during scatter, ordx later)
    unsigned char* srt = (unsigned char*)(cnt + MNODE); // [6400]

    const int g     = blockIdx.x;
    const int tid   = threadIdx.x;
    const int lane  = tid & 31;
    const int wid   = tid >> 5;
    const int nbase = g * MNODE;
    const int ebase = g * EPG;

    // ---------------- degree counts ----------------
    for (int i = tid; i < MNODE; i += NTHREADS) cnt[i] = 0;
    __syncthreads();
    for (int e = tid; e < EPG; e += NTHREADS) {
        int dl = edst[ebase + e] - nbase;
        atomicAdd(&cnt[dl], 1);
    }
    __syncthreads();

    // ---------------- exclusive prefix (warp 0, chunked scan) ----------------
    if (wid == 0) {
        int base = lane * 7;
        int vals[7];
        int lsum = 0;
        #pragma unroll
        for (int j = 0; j < 7; ++j) {
            int idx = base + j;
            int v = (idx < MNODE) ? cnt[idx] : 0;
            vals[j] = lsum;
            lsum += v;
        }
        int run = lsum;
        #pragma unroll
        for (int o = 1; o < 32; o <<= 1) {
            int t = __shfl_up_sync(0xffffffffu, run, o);
            if (lane >= o) run += t;
        }
        int excl = run - lsum;
        #pragma unroll
        for (int j = 0; j < 7; ++j) {
            int idx = base + j;
            if (idx < MNODE) start[idx] = excl + vals[j];
        }
        if (lane == 31) start[MNODE] = excl + lsum;
    }
    __syncthreads();

    // dinv = rsqrt(deg+1); cnt -> running positions for scatter
    for (int i = tid; i < MNODE; i += NTHREADS) {
        dinv[i] = rsqrtf((float)cnt[i] + 1.0f);
        cnt[i]  = start[i];
    }
    __syncthreads();

    // ---------------- CSR scatter (src lists per dst, as u8) ----------------
    for (int e = tid; e < EPG; e += NTHREADS) {
        int dl = edst[ebase + e] - nbase;
        int sl = esrc[ebase + e] - nbase;
        int slot = atomicAdd(&cnt[dl], 1);
        srt[slot] = (unsigned char)sl;
    }
    __syncthreads();

    // ============== Layer 1: yb = dinv * (x @ W1) ==============
    for (int it = tid; it < MNODE*32; it += NTHREADS) {
        int row = it >> 5, col = it & 31;
        const float* xr = x + (long)(nbase + row) * DIMIN;
        float s = 0.f;
        #pragma unroll 8
        for (int k = 0; k < DIMIN; ++k)
            s += __ldg(xr + k) * __ldg(W1 + k*32 + col);
        yb[it] = dinv[row] * s;
    }
    __syncthreads();
    // aggregate (pull via CSR) -> h1
    for (int node = wid; node < MNODE; node += NWARP) {
        int s0 = start[node], s1 = start[node+1];
        float acc = 0.f;
        for (int j = s0; j < s1; ++j) {
            int sl = srt[j];
            acc += yb[sl*32 + lane];
        }
        float v = dinv[node] * (acc + yb[node*32 + lane]) + __ldg(b1 + lane);
        h1[node*S3 + lane] = tanhf(v);
    }
    __syncthreads();

    // ============== Layer 2 ==============
    for (int it = tid; it < MNODE*32; it += NTHREADS) {
        int row = it >> 5, col = it & 31;
        const float* hr = h1 + row*S3;
        float s = 0.f;
        #pragma unroll
        for (int k = 0; k < 32; ++k)
            s += hr[k] * __ldg(W2 + k*32 + col);
        yb[it] = dinv[row] * s;
    }
    __syncthreads();
    for (int node = wid; node < MNODE; node += NWARP) {
        int s0 = start[node], s1 = start[node+1];
        float acc = 0.f;
        for (int j = s0; j < s1; ++j) acc += yb[(int)srt[j]*32 + lane];
        float v = dinv[node] * (acc + yb[node*32 + lane]) + __ldg(b2 + lane);
        h2[node*S3 + lane] = tanhf(v);
    }
    __syncthreads();

    // ============== Layer 3 ==============
    for (int it = tid; it < MNODE*32; it += NTHREADS) {
        int row = it >> 5, col = it & 31;
        const float* hr = h2 + row*S3;
        float s = 0.f;
        #pragma unroll
        for (int k = 0; k < 32; ++k)
            s += hr[k] * __ldg(W3 + k*32 + col);
        yb[it] = dinv[row] * s;
    }
    __syncthreads();
    for (int node = wid; node < MNODE; node += NWARP) {
        int s0 = start[node], s1 = start[node+1];
        float acc = 0.f;
        for (int j = s0; j < s1; ++j) acc += yb[(int)srt[j]*32 + lane];
        float v = dinv[node] * (acc + yb[node*32 + lane]) + __ldg(b3 + lane);
        h3[node*S3 + lane] = tanhf(v);
    }
    __syncthreads();

    // ============== Layer 4 (Fout = 1) ==============
    for (int node = wid; node < MNODE; node += NWARP) {
        float v = h3[node*S3 + lane] * __ldg(W4 + lane);
        #pragma unroll
        for (int o = 16; o; o >>= 1) v += __shfl_xor_sync(0xffffffffu, v, o);
        if (lane == 0) y4[node] = dinv[node] * v;
    }
    __syncthreads();
    for (int node = tid; node < MNODE; node += NTHREADS) {
        int s0 = start[node], s1 = start[node+1];
        float acc = 0.f;
        for (int j = s0; j < s1; ++j) acc += y4[srt[j]];
        h4[node] = tanhf(dinv[node] * (acc + y4[node]) + __ldg(b4));
    }
    __syncthreads();

    // ============== SortPool: top-30 by h4, stable desc (ties -> lower idx) ==============
    int* ordx = cnt;   // cnt no longer needed
    for (int i = tid; i < MNODE; i += NTHREADS) {
        float v = h4[i];
        int rank = 0;
        for (int j = 0; j < MNODE; ++j) {
            float vj = h4[j];
            rank += (vj > v) || (vj == v && j < i);
        }
        if (rank < KTOP) ordx[rank] = i;
    }
    __syncthreads();

    // conv scratch overlays yb (free after layer 4)
    float* c1 = yb;            // [16][30] = 480
    float* pp = yb + 480;      // [16][15] = 240
    float* c2 = yb + 720;      // [32][11] = 352
    float* hl = yb + 1072;     // [128]

    // ============== Conv1: [16 out][97 taps], stride 97 over top-K rows ==============
    for (int it = tid; it < 16*KTOP; it += NTHREADS) {
        int o = it / KTOP, k = it % KTOP;
        int node = ordx[k];
        const float* w = cW1 + o*97;
        const float* a1 = h1 + node*S3;
        const float* a2 = h2 + node*S3;
        const float* a3 = h3 + node*S3;
        float s = __ldg(cb1 + o);
        #pragma unroll
        for (int f = 0; f < 32; ++f) s += a1[f] * __ldg(w + f);
        #pragma unroll
        for (int f = 0; f < 32; ++f) s += a2[f] * __ldg(w + 32 + f);
        #pragma unroll
        for (int f = 0; f < 32; ++f) s += a3[f] * __ldg(w + 64 + f);
        s += h4[node] * __ldg(w + 96);
        c1[o*KTOP + k] = fmaxf(s, 0.f);
    }
    __syncthreads();

    // ============== MaxPool1d(2,2): [16][30] -> [16][15] ==============
    for (int it = tid; it < 16*15; it += NTHREADS) {
        int o = it / 15, t = it % 15;
        pp[it] = fmaxf(c1[o*KTOP + 2*t], c1[o*KTOP + 2*t + 1]);
    }
    __syncthreads();

    // ============== Conv2: 16->32, k=5, valid -> [32][11] ==============
    for (int it = tid; it < 32*11; it += NTHREADS) {
        int o = it / 11, t = it % 11;
        const float* w = cW2 + o*80;
        float s = __ldg(cb2 + o);
        #pragma unroll
        for (int i = 0; i < 16; ++i)
            #pragma unroll
            for (int j = 0; j < 5; ++j)
                s += __ldg(w + i*5 + j) * pp[i*15 + t + j];
        c2[it] = fmaxf(s, 0.f);   // flat index = o*11+t matches reshape(B,352)
    }
    __syncthreads();

    // ============== Linear 352 -> 128, ReLU ==============
    for (int h = tid; h < 128; h += NTHREADS) {
        float s = __ldg(lb1 + h);
        #pragma unroll 4
        for (int i = 0; i < 352; ++i)
            s += c2[i] * __ldg(lW1 + i*128 + h);
        hl[h] = fmaxf(s, 0.f);
    }
    __syncthreads();

    // ============== Linear 128 -> 1, sigmoid ==============
    if (wid == 0) {
        float v = 0.f;
        #pragma unroll
        for (int i = lane; i < 128; i += 32)
            v += hl[i] * __ldg(lW2 + i);
        #pragma unroll
        for (int o = 16; o; o >>= 1) v += __shfl_xor_sync(0xffffffffu, v, o);
        if (lane == 0)
            out[g] = 1.0f / (1.0f + expf(-(v + __ldg(lb2))));
    }
}

extern "C" void kernel_launch(void* const* d_in, const int* in_sizes, int n_in,
                              void* d_out, int out_size)
{
    const float* x    = (const float*)d_in[0];
    const int*   ei   = (const int*)  d_in[1];   // [2, E]: src then dst
    // d_in[2] = batch (unused; layout is fixed block-contiguous)
    const float* W1   = (const float*)d_in[3];
    const float* b1   = (const float*)d_in[4];
    const float* W2   = (const float*)d_in[5];
    const float* b2   = (const float*)d_in[6];
    const float* W3   = (const float*)d_in[7];
    const float* b3   = (const float*)d_in[8];
    const float* W4   = (const float*)d_in[9];
    const float* b4   = (const float*)d_in[10];
    const float* cW1  = (const float*)d_in[11];
    const float* cb1  = (const float*)d_in[12];
    const float* cW2  = (const float*)d_in[13];
    const float* cb2  = (const float*)d_in[14];
    const float* lW1  = (const float*)d_in[15];
    const float* lb1  = (const float*)d_in[16];
    const float* lW2  = (const float*)d_in[17];
    const float* lb2  = (const float*)d_in[18];

    const int E = in_sizes[1] / 2;
    const int* esrc = ei;
    const int* edst = ei + E;

    cudaFuncSetAttribute(dgcnn_fused_kernel,
                         cudaFuncAttributeMaxDynamicSharedMemorySize, SM_BYTES);

    dgcnn_fused_kernel<<<BGRAPH, NTHREADS, SM_BYTES>>>(
        x, esrc, edst,
        W1, b1, W2, b2, W3, b3, W4, b4,
        cW1, cb1, cW2, cb2, lW1, lb1, lW2, lb2,
        (float*)d_out);
}

// round 4
// speedup vs baseline: 1.2479x; 1.2479x over previous
#include <cuda_runtime.h>

// Fixed problem shape
#define BGRAPH   512
#define MNODE    200
#define EPG      6400
#define DIMIN    128
#define KTOP     30
#define NTHREADS 256
#define NWARP    8
#define SH       33      // hcur row stride (conflict-free)
#define SX       130     // x-tile row stride (float2-aligned, conflict-free)

// Global staging for h1,h2 (gathered only for top-K rows at the end). 26 MB.
__device__ float g_h12[(size_t)BGRAPH * 2 * MNODE * 32];

// SMEM: hcur[200*33] | yb[200*32] | xs[4160] | dinv[200] | start[201] int | srt[6400] u8
#define SM_FLOATS (MNODE*SH + MNODE*32 + 4160 + MNODE)
#define SM_BYTES  (SM_FLOATS*4 + 201*4 + EPG)   // 76644 B -> 3 CTAs/SM

__global__ __launch_bounds__(NTHREADS, 3)
void dgcnn_fused_kernel(const float* __restrict__ x,
                        const int*   __restrict__ esrc,
                        const int*   __restrict__ edst,
                        const float* __restrict__ W1, const float* __restrict__ b1,
                        const float* __restrict__ W2, const float* __restrict__ b2,
                        const float* __restrict__ W3, const float* __restrict__ b3,
                        const float* __restrict__ W4, const float* __restrict__ b4,
                        const float* __restrict__ cW1, const float* __restrict__ cb1,
                        const float* __restrict__ cW2, const float* __restrict__ cb2,
                        const float* __restrict__ lW1, const float* __restrict__ lb1,
                        const float* __restrict__ lW2, const float* __restrict__ lb2,
                        float* __restrict__ out)
{
    extern __shared__ char smem[];
    float* hcur = (float*)smem;                 // [200][33]; overlaid by W1s[4096] in layer 1
    float* yb   = hcur + MNODE*SH;              // [200][32]
    float* xs   = yb + MNODE*32;                // 4160-float multi-purpose region
    float* dinv = xs + 4160;                    // [200]
    int*   start = (int*)(dinv + MNODE);        // [201]
    unsigned char* srt = (unsigned char*)(start + 201); // [6400]

    // xs-region overlays (phase-disjoint):
    int*   cnt  = (int*)xs;                     // build phase: [200]
    //   layer 1: xs = x tile [32][130]
    //   layers 2/3: Wks = xs[0..1024)
    float* h4   = xs;                           // [200]     (post layer-3)
    float* y4   = xs + 200;                     // [200]
    int*   ordx = (int*)(xs + 400);             // [30]
    float* h1t  = xs + 440;                     // [30*32]
    float* h2t  = xs + 1400;                    // [30*32]
    float* c1   = xs + 2360;                    // [16*30]
    float* pp   = xs + 2840;                    // [16*15]
    float* c2   = xs + 3080;                    // [32*11]
    float* hl   = xs + 3432;                    // [128]
    float* hl2  = xs + 3560;                    // [128]

    const int g     = blockIdx.x;
    const int tid   = threadIdx.x;
    const int lane  = tid & 31;
    const int wid   = tid >> 5;
    const int nbase = g * MNODE;
    const int ebase = g * EPG;

    // ---------------- degree counts ----------------
    for (int i = tid; i < MNODE; i += NTHREADS) cnt[i] = 0;
    __syncthreads();
    for (int e = tid; e < EPG; e += NTHREADS)
        atomicAdd(&cnt[edst[ebase + e] - nbase], 1);
    __syncthreads();

    // ---------------- exclusive prefix (warp 0) ----------------
    if (wid == 0) {
        int base = lane * 7;
        int vals[7];
        int lsum = 0;
        #pragma unroll
        for (int j = 0; j < 7; ++j) {
            int idx = base + j;
            int v = (idx < MNODE) ? cnt[idx] : 0;
            vals[j] = lsum; lsum += v;
        }
        int run = lsum;
        #pragma unroll
        for (int o = 1; o < 32; o <<= 1) {
            int t = __shfl_up_sync(0xffffffffu, run, o);
            if (lane >= o) run += t;
        }
        int excl = run - lsum;
        #pragma unroll
        for (int j = 0; j < 7; ++j) {
            int idx = base + j;
            if (idx < MNODE) start[idx] = excl + vals[j];
        }
        if (lane == 31) start[MNODE] = excl + lsum;
    }
    __syncthreads();

    for (int i = tid; i < MNODE; i += NTHREADS) {
        dinv[i] = rsqrtf((float)cnt[i] + 1.0f);
        cnt[i]  = start[i];
    }
    __syncthreads();

    // ---------------- CSR scatter (u8 src lists per dst) ----------------
    for (int e = tid; e < EPG; e += NTHREADS) {
        int dl = edst[ebase + e] - nbase;
        int sl = esrc[ebase + e] - nbase;
        int slot = atomicAdd(&cnt[dl], 1);
        srt[slot] = (unsigned char)sl;
    }
    __syncthreads();

    // ============== Layer 1: yb = dinv * (x @ W1)  (all-SMEM tiled) ==============
    // Stage W1 (128x32 = 16 KB) into hcur region (dead until layer-2)
    {
        float4* W1s4 = (float4*)hcur;
        for (int i = tid; i < 1024; i += NTHREADS)
            W1s4[i] = __ldg((const float4*)W1 + i);
    }
    __syncthreads();
    {
        const int rowt = tid >> 3;      // 0..31
        const int cg   = tid & 7;       // 0..7  (4 cols each)
        for (int c = 0; c < 7; ++c) {
            int r0 = c * 32;
            int nr = min(32, MNODE - r0);
            // stage x rows [r0, r0+nr) into xs (float2, coalesced)
            for (int i = tid; i < nr * 64; i += NTHREADS) {
                int row = i >> 6, k2 = i & 63;
                float2 v = __ldg((const float2*)(x + (size_t)(nbase + r0 + row) * DIMIN) + k2);
                *(float2*)(xs + row * SX + 2 * k2) = v;
            }
            __syncthreads();
            if (rowt < nr) {
                const float* xr = xs + rowt * SX;
                const float* wc = hcur + 4 * cg;
                float a0 = 0.f, a1 = 0.f, a2 = 0.f, a3 = 0.f;
                #pragma unroll 8
                for (int k = 0; k < DIMIN; ++k) {
                    float xv = xr[k];
                    float4 w = *(const float4*)(wc + k * 32);
                    a0 += xv * w.x; a1 += xv * w.y; a2 += xv * w.z; a3 += xv * w.w;
                }
                float d = dinv[r0 + rowt];
                *(float4*)(yb + (r0 + rowt) * 32 + 4 * cg) =
                    make_float4(a0 * d, a1 * d, a2 * d, a3 * d);
            }
            __syncthreads();
        }
    }

    // aggregate (pull via CSR) -> hcur = h1 ; also stage to global
    {
        float bv = __ldg(b1 + lane);
        for (int node = wid; node < MNODE; node += NWARP) {
            int s0 = start[node], s1 = start[node + 1];
            float a0 = 0.f, a1 = 0.f, a2 = 0.f, a3 = 0.f;
            int j = s0;
            for (; j + 4 <= s1; j += 4) {
                int i0 = srt[j], i1 = srt[j+1], i2 = srt[j+2], i3 = srt[j+3];
                a0 += yb[i0*32 + lane]; a1 += yb[i1*32 + lane];
                a2 += yb[i2*32 + lane]; a3 += yb[i3*32 + lane];
            }
            for (; j < s1; ++j) a0 += yb[(int)srt[j]*32 + lane];
            float acc = (a0 + a1) + (a2 + a3);
            float v = tanhf(dinv[node] * (acc + yb[node*32 + lane]) + bv);
            hcur[node*SH + lane] = v;
            g_h12[((size_t)g * 2 + 0) * MNODE * 32 + node * 32 + lane] = v;
        }
    }
    __syncthreads();

    // ============== Layers 2 and 3 (identical structure) ==============
    #pragma unroll 1
    for (int L = 0; L < 2; ++L) {
        const float* W = L ? W3 : W2;
        const float* b = L ? b3 : b2;
        // stage W (32x32) into xs[0..1024)
        for (int i = tid; i < 256; i += NTHREADS)
            ((float4*)xs)[i] = __ldg((const float4*)W + i);
        __syncthreads();
        for (int it = tid; it < MNODE * 8; it += NTHREADS) {
            int row = it >> 3, cg = it & 7;
            const float* hr = hcur + row * SH;
            const float* wc = xs + 4 * cg;
            float a0 = 0.f, a1 = 0.f, a2 = 0.f, a3 = 0.f;
            #pragma unroll
            for (int k = 0; k < 32; ++k) {
                float hv = hr[k];
                float4 w = *(const float4*)(wc + k * 32);
                a0 += hv * w.x; a1 += hv * w.y; a2 += hv * w.z; a3 += hv * w.w;
            }
            float d = dinv[row];
            *(float4*)(yb + row * 32 + 4 * cg) = make_float4(a0*d, a1*d, a2*d, a3*d);
        }
        __syncthreads();
        float bv = __ldg(b + lane);
        for (int node = wid; node < MNODE; node += NWARP) {
            int s0 = start[node], s1 = start[node + 1];
            float a0 = 0.f, a1 = 0.f, a2 = 0.f, a3 = 0.f;
            int j = s0;
            for (; j + 4 <= s1; j += 4) {
                int i0 = srt[j], i1 = srt[j+1], i2 = srt[j+2], i3 = srt[j+3];
                a0 += yb[i0*32 + lane]; a1 += yb[i1*32 + lane];
                a2 += yb[i2*32 + lane]; a3 += yb[i3*32 + lane];
            }
            for (; j < s1; ++j) a0 += yb[(int)srt[j]*32 + lane];
            float acc = (a0 + a1) + (a2 + a3);
            float v = tanhf(dinv[node] * (acc + yb[node*32 + lane]) + bv);
            hcur[node*SH + lane] = v;
            if (L == 0)
                g_h12[((size_t)g * 2 + 1) * MNODE * 32 + node * 32 + lane] = v;
        }
        __syncthreads();
    }

    // ============== Layer 4 (Fout = 1): y4 = dinv * (h3 @ W4) ==============
    {
        float w4v = __ldg(W4 + lane);
        for (int node = wid; node < MNODE; node += NWARP) {
            float v = hcur[node*SH + lane] * w4v;
            #pragma unroll
            for (int o = 16; o; o >>= 1) v += __shfl_xor_sync(0xffffffffu, v, o);
            if (lane == 0) y4[node] = dinv[node] * v;
        }
    }
    __syncthreads();
    {
        float b4v = __ldg(b4);
        for (int node = tid; node < MNODE; node += NTHREADS) {
            int s0 = start[node], s1 = start[node + 1];
            float acc = 0.f;
            for (int j = s0; j < s1; ++j) acc += y4[srt[j]];
            h4[node] = tanhf(dinv[node] * (acc + y4[node]) + b4v);
        }
    }
    __syncthreads();

    // ============== SortPool: top-30 by h4, stable desc ==============
    for (int i = tid; i < MNODE; i += NTHREADS) {
        float v = h4[i];
        int rank = 0;
        for (int j = 0; j < MNODE; ++j) {
            float vj = h4[j];
            rank += (vj > v) || (vj == v && j < i);
        }
        if (rank < KTOP) ordx[rank] = i;
    }
    __syncthreads();

    // gather h1,h2 rows of top-K nodes from global staging
    for (int i = tid; i < KTOP * 32 * 2; i += NTHREADS) {
        int L = (i >= KTOP * 32);
        int idx = i - L * KTOP * 32;
        int slot = idx >> 5, f = idx & 31;
        int node = ordx[slot];
        float v = g_h12[((size_t)g * 2 + L) * MNODE * 32 + node * 32 + f];
        (L ? h2t : h1t)[idx] = v;
    }
    __syncthreads();

    // ============== Conv1: 1->16, taps 97, stride 97 ==============
    for (int it = tid; it < 16 * KTOP; it += NTHREADS) {
        int o = it / KTOP, k = it % KTOP;
        int node = ordx[k];
        const float* w  = cW1 + o * 97;
        const float* a1 = h1t + k * 32;
        const float* a2 = h2t + k * 32;
        const float* a3 = hcur + node * SH;
        float s = __ldg(cb1 + o);
        #pragma unroll 8
        for (int f = 0; f < 32; ++f) s += a1[f] * __ldg(w + f);
        #pragma unroll 8
        for (int f = 0; f < 32; ++f) s += a2[f] * __ldg(w + 32 + f);
        #pragma unroll 8
        for (int f = 0; f < 32; ++f) s += a3[f] * __ldg(w + 64 + f);
        s += h4[node] * __ldg(w + 96);
        c1[o * KTOP + k] = fmaxf(s, 0.f);
    }
    __syncthreads();

    // ============== MaxPool1d(2,2) ==============
    for (int it = tid; it < 16 * 15; it += NTHREADS) {
        int o = it / 15, t = it % 15;
        pp[it] = fmaxf(c1[o * KTOP + 2 * t], c1[o * KTOP + 2 * t + 1]);
    }
    __syncthreads();

    // ============== Conv2: 16->32, k=5 -> [32][11] ==============
    for (int it = tid; it < 32 * 11; it += NTHREADS) {
        int o = it / 11, t = it % 11;
        const float* w = cW2 + o * 80;
        float s = __ldg(cb2 + o);
        #pragma unroll
        for (int i = 0; i < 16; ++i)
            #pragma unroll
            for (int j = 0; j < 5; ++j)
                s += __ldg(w + i * 5 + j) * pp[i * 15 + t + j];
        c2[it] = fmaxf(s, 0.f);
    }
    __syncthreads();

    // ============== Linear 352 -> 128 (split-2) ==============
    {
        int h = tid & 127, half = tid >> 7;
        const float* base = lW1 + h;
        float s = half ? 0.f : __ldg(lb1 + h);
        int i0 = half * 176;
        #pragma unroll 8
        for (int i = i0; i < i0 + 176; ++i)
            s += c2[i] * __ldg(base + i * 128);
        (half ? hl2 : hl)[h] = s;
    }
    __syncthreads();

    // ============== Linear 128 -> 1, sigmoid ==============
    if (wid == 0) {
        float v = 0.f;
        #pragma unroll
        for (int i = lane; i < 128; i += 32) {
            float hv = fmaxf(hl[i] + hl2[i], 0.f);
            v += hv * __ldg(lW2 + i);
        }
        #pragma unroll
        for (int o = 16; o; o >>= 1) v += __shfl_xor_sync(0xffffffffu, v, o);
        if (lane == 0)
            out[g] = 1.0f / (1.0f + expf(-(v + __ldg(lb2))));
    }
}

extern "C" void kernel_launch(void* const* d_in, const int* in_sizes, int n_in,
                              void* d_out, int out_size)
{
    const float* x    = (const float*)d_in[0];
    const int*   ei   = (const int*)  d_in[1];
    const float* W1   = (const float*)d_in[3];
    const float* b1   = (const float*)d_in[4];
    const float* W2   = (const float*)d_in[5];
    const float* b2   = (const float*)d_in[6];
    const float* W3   = (const float*)d_in[7];
    const float* b3   = (const float*)d_in[8];
    const float* W4   = (const float*)d_in[9];
    const float* b4   = (const float*)d_in[10];
    const float* cW1  = (const float*)d_in[11];
    const float* cb1  = (const float*)d_in[12];
    const float* cW2  = (const float*)d_in[13];
    const float* cb2  = (const float*)d_in[14];
    const float* lW1  = (const float*)d_in[15];
    const float* lb1  = (const float*)d_in[16];
    const float* lW2  = (const float*)d_in[17];
    const float* lb2  = (const float*)d_in[18];

    const int E = in_sizes[1] / 2;
    const int* esrc = ei;
    const int* edst = ei + E;

    cudaFuncSetAttribute(dgcnn_fused_kernel,
                         cudaFuncAttributeMaxDynamicSharedMemorySize, SM_BYTES);

    dgcnn_fused_kernel<<<BGRAPH, NTHREADS, SM_BYTES>>>(
        x, esrc, edst,
        W1, b1, W2, b2, W3, b3, W4, b4,
        cW1, cb1, cW2, cb2, lW1, lb1, lW2, lb2,
        (float*)d_out);
}